// round 11
// baseline (speedup 1.0000x reference)
#include <cuda_runtime.h>
#include <cuda_fp16.h>
#include <mma.h>
using namespace nvcuda;

#define V 8192
#define E 262144
#define D 128
#define SLOTS 128           // hash slots per row (power of 2)
#define GB 256              // gemm grid: V / 32 rows per block

// dynamic smem: Whi(32K) Wlo(32K) Ahi(8K) Alo(8K) C(16K) = 96 KB
#define GEMM_SMEM_BYTES (16384*2*2 + 4096*2*2 + 4096*4)

// ---------------- scratch (device globals; no allocations allowed) ----------
__device__ __half             g_hwh[V * D];      // hw in fp16 (2 MB, L2-resident)
__device__ float              g_s1[V];           // hw[v] . att[:128]  (exact fp32)
__device__ float              g_s2[V];           // hw[v] . att[128:]
__device__ float              g_Spart[GB * D];   // per-block colsum partials
__device__ float              g_S[D];            // reduced colsum of hw
__device__ unsigned long long g_ew64[(size_t)V * SLOTS]; // (idx+1)<<29|dst<<16|half(w)
__device__ int                g_is64;            // edge_index dtype flag

// =================== K1: tensor-core GEMM hw = h @ W^T (fp16-split, smem) ====
// Block: 32 rows x 128 cols. W converted to fp16 hi/lo in smem (per block),
// A rows likewise. 8 warps: warp w owns col-tile w (16 cols), 2 row-tiles,
// K loop 8x16, 3 HMMA per step (hi*hi + hi*lo + lo*hi; missing lo*lo ~2^-22).
// Accumulators staged in fp32 smem; epilogue: fp16 store + exact s1/s2 + colsum.
__global__ void __launch_bounds__(256) k_gemm(const float* __restrict__ h,
                                              const float* __restrict__ Wm,
                                              const float* __restrict__ att,
                                              const int* __restrict__ e32) {
    extern __shared__ char dynsmem[];
    __half* sWhi = (__half*)dynsmem;          // [128][128] = W[col][k]
    __half* sWlo = sWhi + 16384;
    __half* sAhi = sWlo + 16384;              // [32][128]
    __half* sAlo = sAhi + 4096;
    float*  sC   = (float*)(sAlo + 4096);     // [32][128] fp32 result

    int tid = threadIdx.x;
    int warpId = tid >> 5, lane = tid & 31;
    int row0 = blockIdx.x * 32;

    // int64/int32 detection (block 0): int64 values < 2^13 => odd words all 0
    if (blockIdx.x == 0) {
        __shared__ int flag;
        if (tid == 0) flag = 0;
        __syncthreads();
        if (e32[2 * tid + 1] != 0) atomicExch(&flag, 1);
        __syncthreads();
        if (tid == 0) g_is64 = (flag == 0) ? 1 : 0;
    }

    // ---- convert W (16384 floats): 16 float4 per thread ----
#pragma unroll
    for (int j = 0; j < 16; j++) {
        int i4 = tid + j * 256;
        float4 v = *(const float4*)(Wm + (size_t)i4 * 4);
        __half hx = __float2half_rn(v.x), hy = __float2half_rn(v.y);
        __half hz = __float2half_rn(v.z), hw_ = __float2half_rn(v.w);
        __half2 ph0 = __halves2half2(hx, hy), ph1 = __halves2half2(hz, hw_);
        __half lx = __float2half_rn(v.x - __half2float(hx));
        __half ly = __float2half_rn(v.y - __half2float(hy));
        __half lz = __float2half_rn(v.z - __half2float(hz));
        __half lw = __float2half_rn(v.w - __half2float(hw_));
        __half2 pl0 = __halves2half2(lx, ly), pl1 = __halves2half2(lz, lw);
        uint2 uh, ul;
        uh.x = *(unsigned*)&ph0; uh.y = *(unsigned*)&ph1;
        ul.x = *(unsigned*)&pl0; ul.y = *(unsigned*)&pl1;
        *(uint2*)(sWhi + (size_t)i4 * 4) = uh;
        *(uint2*)(sWlo + (size_t)i4 * 4) = ul;
    }
    // ---- convert A (32 rows x 128 = 4096 floats): 4 float4 per thread ----
#pragma unroll
    for (int j = 0; j < 4; j++) {
        int i4 = tid + j * 256;
        float4 v = *(const float4*)(h + (size_t)row0 * D + (size_t)i4 * 4);
        __half hx = __float2half_rn(v.x), hy = __float2half_rn(v.y);
        __half hz = __float2half_rn(v.z), hw_ = __float2half_rn(v.w);
        __half2 ph0 = __halves2half2(hx, hy), ph1 = __halves2half2(hz, hw_);
        __half lx = __float2half_rn(v.x - __half2float(hx));
        __half ly = __float2half_rn(v.y - __half2float(hy));
        __half lz = __float2half_rn(v.z - __half2float(hz));
        __half lw = __float2half_rn(v.w - __half2float(hw_));
        __half2 pl0 = __halves2half2(lx, ly), pl1 = __halves2half2(lz, lw);
        uint2 uh, ul;
        uh.x = *(unsigned*)&ph0; uh.y = *(unsigned*)&ph1;
        ul.x = *(unsigned*)&pl0; ul.y = *(unsigned*)&pl1;
        *(uint2*)(sAhi + (size_t)i4 * 4) = uh;
        *(uint2*)(sAlo + (size_t)i4 * 4) = ul;
    }
    __syncthreads();

    // ---- wmma: warp w -> col-tile w; row-tiles 0,1 ----
    int ct = warpId;
#pragma unroll
    for (int rt = 0; rt < 2; rt++) {
        wmma::fragment<wmma::accumulator, 16, 16, 16, float> acc;
        wmma::fill_fragment(acc, 0.f);
#pragma unroll
        for (int k0 = 0; k0 < 8; k0++) {
            wmma::fragment<wmma::matrix_a, 16, 16, 16, __half, wmma::row_major> ahi, alo;
            wmma::load_matrix_sync(ahi, sAhi + rt * 16 * D + k0 * 16, D);
            wmma::load_matrix_sync(alo, sAlo + rt * 16 * D + k0 * 16, D);
            wmma::fragment<wmma::matrix_b, 16, 16, 16, __half, wmma::col_major> bhi, blo;
            wmma::load_matrix_sync(bhi, sWhi + ct * 16 * D + k0 * 16, D);
            wmma::load_matrix_sync(blo, sWlo + ct * 16 * D + k0 * 16, D);
            wmma::mma_sync(acc, ahi, bhi, acc);
            wmma::mma_sync(acc, ahi, blo, acc);
            wmma::mma_sync(acc, alo, bhi, acc);
        }
        wmma::store_matrix_sync(sC + rt * 16 * D + ct * 16, acc, D, wmma::mem_row_major);
    }
    __syncthreads();

    // ---- epilogue (all from fp32 sC) ----
    // fp16 store of hw: 4 float4-groups per thread
#pragma unroll
    for (int j = 0; j < 4; j++) {
        int i4 = tid + j * 256;
        int row = i4 >> 5, off = (i4 & 31) * 4;
        float4 v = *(const float4*)(sC + row * D + off);
        __half2 q0 = __floats2half2_rn(v.x, v.y);
        __half2 q1 = __floats2half2_rn(v.z, v.w);
        uint2 u;
        u.x = *(unsigned*)&q0; u.y = *(unsigned*)&q1;
        *(uint2*)(g_hwh + (size_t)(row0 + row) * D + off) = u;
    }
    // s1/s2: warp w owns rows 4w..4w+3; lane dots 4 cols, shfl-reduce
    {
        float4 a1 = *(const float4*)(att + lane * 4);
        float4 a2 = *(const float4*)(att + D + lane * 4);
#pragma unroll
        for (int r = 0; r < 4; r++) {
            int row = warpId * 4 + r;
            float4 cv = *(const float4*)(sC + row * D + lane * 4);
            float s1 = cv.x * a1.x + cv.y * a1.y + cv.z * a1.z + cv.w * a1.w;
            float s2 = cv.x * a2.x + cv.y * a2.y + cv.z * a2.z + cv.w * a2.w;
#pragma unroll
            for (int o = 16; o; o >>= 1) {
                s1 += __shfl_xor_sync(0xffffffffu, s1, o);
                s2 += __shfl_xor_sync(0xffffffffu, s2, o);
            }
            if (lane == 0) { g_s1[row0 + row] = s1; g_s2[row0 + row] = s2; }
        }
    }
    // colsum partial: threads 0..127, column tid over 32 rows (conflict-free)
    if (tid < D) {
        float s = 0.f;
#pragma unroll 8
        for (int r = 0; r < 32; r++) s += sC[r * D + tid];
        g_Spart[blockIdx.x * D + tid] = s;
    }
}

// =================== K2: per-edge logit + hash insert (dedup by atomicMax) ===
// Record: bits[0:16)=half(w), [16:29)=dst, [29:48)=edge_idx+1  (max idx wins)
__global__ void k_scatter(const int* __restrict__ e32) {
    // block 0: reduce colsum partials -> g_S (k_row reads it later)
    if (blockIdx.x == 0 && threadIdx.x < D) {
        float s = 0.f;
#pragma unroll 16
        for (int b = 0; b < GB; b++) s += g_Spart[b * D + threadIdx.x];
        g_S[threadIdx.x] = s;
    }
    int e = blockIdx.x * blockDim.x + threadIdx.x;
    if (e >= E) return;
    int src, dst;
    if (g_is64) {
        src = ((const int2*)e32)[e].x;
        dst = ((const int2*)e32)[E + e].x;
    } else {
        src = e32[e];
        dst = e32[E + e];
    }
    float a = g_s1[src] + g_s2[dst];
    a = a > 0.f ? a : 0.2f * a;                       // LeakyReLU(0.2)
    float w = expm1f(a);                              // exp(a) - 1
    unsigned wh = (unsigned)__half_as_ushort(__float2half_rn(w));
    unsigned long long rec = ((unsigned long long)(unsigned)(e + 1) << 29)
                           | ((unsigned long long)(unsigned)dst << 16) | wh;
    unsigned slot = ((unsigned)dst * 2654435761u) >> 25;   // 7-bit hash
    unsigned long long* tab = g_ew64 + (size_t)src * SLOTS;
    for (int probe = 0; probe < SLOTS; probe++) {
        unsigned long long old = atomicCAS(&tab[slot], 0ULL, rec);
        if (old == 0ULL) break;                            // claimed empty slot
        if (((unsigned)(old >> 16) & 0x1FFFu) == (unsigned)dst) {
            atomicMax(&tab[slot], rec);                    // last-write-wins
            break;
        }
        slot = (slot + 1) & (SLOTS - 1);
    }
}

// =================== K3: slot scan + compact + gather + normalize ============
__global__ void __launch_bounds__(256, 5) k_row(float* __restrict__ out) {
    __shared__ uint2 sm[8][SLOTS];     // {dst, float bits of w}
    int wid = threadIdx.x >> 5, lane = threadIdx.x & 31;
    int row = blockIdx.x * 8 + wid;
    unsigned long long* tab = g_ew64 + (size_t)row * SLOTS;

    float dsum = 0.f;
    int cnt = 0;
#pragma unroll
    for (int rnd = 0; rnd < SLOTS / 32; rnd++) {
        int s = rnd * 32 + lane;
        unsigned long long v = tab[s];
        tab[s] = 0ULL;                                   // replay-safe re-zero
        unsigned mask = __ballot_sync(0xffffffffu, v != 0ULL);
        if (v != 0ULL) {
            int pos = cnt + __popc(mask & ((1u << lane) - 1u));
            float w = __half2float(__ushort_as_half((unsigned short)(v & 0xFFFFu)));
            sm[wid][pos] = make_uint2((unsigned)(v >> 16) & 0x1FFFu,
                                      __float_as_uint(w));
            dsum += w;
        }
        cnt += __popc(mask);
    }
    int dpad = (cnt + 7) & ~7;
    for (int t = cnt + lane; t < dpad; t += 32)
        sm[wid][t] = make_uint2(0u, 0u);                 // harmless pad (w=0)
    __syncwarp();

    // pair-gather: lanes 0-15 edge A, 16-31 edge B; 16B (8 halves) per lane
    float acc[8];
#pragma unroll
    for (int i = 0; i < 8; i++) acc[i] = 0.f;
    int half_ = lane >> 4;
    int cl = (lane & 15) * 8;
    const __half* hw = g_hwh;

    for (int t = 0; t < dpad; t += 8) {
#pragma unroll
        for (int p = 0; p < 4; p++) {
            uint2 m = sm[wid][t + 2 * p + half_];
            float w = __uint_as_float(m.y);
            uint4 v = *(const uint4*)(hw + (size_t)m.x * D + cl);
            float2 f0 = __half22float2(*(__half2*)&v.x);
            float2 f1 = __half22float2(*(__half2*)&v.y);
            float2 f2 = __half22float2(*(__half2*)&v.z);
            float2 f3 = __half22float2(*(__half2*)&v.w);
            acc[0] += w * f0.x; acc[1] += w * f0.y;
            acc[2] += w * f1.x; acc[3] += w * f1.y;
            acc[4] += w * f2.x; acc[5] += w * f2.y;
            acc[6] += w * f3.x; acc[7] += w * f3.y;
        }
    }

#pragma unroll
    for (int i = 0; i < 8; i++) acc[i] += __shfl_xor_sync(0xffffffffu, acc[i], 16);
#pragma unroll
    for (int o = 16; o; o >>= 1) dsum += __shfl_xor_sync(0xffffffffu, dsum, o);

    float inv = 1.f / ((float)V + dsum);
    if (lane < 16) {
        float4 Sa = *(const float4*)(g_S + cl);
        float4 Sb = *(const float4*)(g_S + cl + 4);
        float4 o0, o1;
        o0.x = (Sa.x + acc[0]) * inv; o0.y = (Sa.y + acc[1]) * inv;
        o0.z = (Sa.z + acc[2]) * inv; o0.w = (Sa.w + acc[3]) * inv;
        o1.x = (Sb.x + acc[4]) * inv; o1.y = (Sb.y + acc[5]) * inv;
        o1.z = (Sb.z + acc[6]) * inv; o1.w = (Sb.w + acc[7]) * inv;
        *(float4*)(out + (size_t)row * D + cl) = o0;
        *(float4*)(out + (size_t)row * D + cl + 4) = o1;
    }
}

// ----------------------------------------------------------------------------
extern "C" void kernel_launch(void* const* d_in, const int* in_sizes, int n_in,
                              void* d_out, int out_size) {
    const float* h   = (const float*)d_in[0];
    const int*   ei  = (const int*)d_in[1];
    const float* Wm  = (const float*)d_in[2];
    const float* att = (const float*)d_in[3];
    float* out = (float*)d_out;

    cudaFuncSetAttribute(k_gemm, cudaFuncAttributeMaxDynamicSharedMemorySize,
                         GEMM_SMEM_BYTES);
    k_gemm<<<GB, 256, GEMM_SMEM_BYTES>>>(h, Wm, att, ei);
    k_scatter<<<E / 256, 256>>>(ei);
    k_row<<<V / 8, 256>>>(out);
}

// round 13
// speedup vs baseline: 1.2664x; 1.2664x over previous
#include <cuda_runtime.h>
#include <cuda_fp16.h>
#include <mma.h>
using namespace nvcuda;

#define V 8192
#define E 262144
#define D 128
#define SLOTS 128           // hash slots per row (power of 2)
#define GB 256              // gemm grid: V / 32 rows per block

// padded smem strides (bank-conflict-free for LDSM: stride mod 128B == 16B)
#define WS 136              // half stride for W/A tiles  (272 B)
#define CS 132              // float stride for C tile    (528 B)

// dynamic smem: Whi+Wlo (2*128*136*2) + Ahi+Alo (2*32*136*2) + C (32*132*4)
#define GEMM_SMEM_BYTES (2*128*WS*2 + 2*32*WS*2 + 32*CS*4)

// ---------------- scratch (device globals; no allocations allowed) ----------
__device__ __half             g_hwh[V * D];      // hw in fp16 (2 MB, L2-resident)
__device__ float              g_s1[V];           // hw[v] . att[:128]  (exact fp32)
__device__ float              g_s2[V];           // hw[v] . att[128:]
__device__ float              g_Spart[GB * D];   // per-block colsum partials
__device__ float              g_S[D];            // reduced colsum of hw
__device__ unsigned long long g_ew64[(size_t)V * SLOTS]; // (idx+1)<<29|dst<<16|half(w)
__device__ int                g_is64;            // edge_index dtype flag

// =================== K1: tensor-core GEMM hw = h @ W^T (fp16-split, smem) ====
// Block: 32 rows x 128 cols. W converted to fp16 hi/lo in padded smem,
// A rows likewise. 8 warps: warp w owns col-tile w (16 cols), 2 row-tiles,
// K loop 8x16, 3 HMMA per step (hi*hi + hi*lo + lo*hi; missing lo*lo ~2^-22).
// Accumulators staged in fp32 smem; epilogue: fp16 store + exact s1/s2 + colsum.
__global__ void __launch_bounds__(256) k_gemm(const float* __restrict__ h,
                                              const float* __restrict__ Wm,
                                              const float* __restrict__ att,
                                              const int* __restrict__ e32) {
    extern __shared__ char dynsmem[];
    __half* sWhi = (__half*)dynsmem;              // [128][WS]  W[col][k]
    __half* sWlo = sWhi + 128 * WS;
    __half* sAhi = sWlo + 128 * WS;               // [32][WS]
    __half* sAlo = sAhi + 32 * WS;
    float*  sC   = (float*)(sAlo + 32 * WS);      // [32][CS] fp32 result

    int tid = threadIdx.x;
    int warpId = tid >> 5, lane = tid & 31;
    int row0 = blockIdx.x * 32;

    // int64/int32 detection (block 0): int64 values < 2^13 => odd words all 0
    if (blockIdx.x == 0) {
        __shared__ int flag;
        if (tid == 0) flag = 0;
        __syncthreads();
        if (e32[2 * tid + 1] != 0) atomicExch(&flag, 1);
        __syncthreads();
        if (tid == 0) g_is64 = (flag == 0) ? 1 : 0;
    }

    // ---- convert W (16384 floats = 4096 float4): 16 float4 per thread ----
#pragma unroll
    for (int j = 0; j < 16; j++) {
        int i4 = tid + j * 256;
        int row = i4 >> 5, c4 = (i4 & 31) * 4;    // row = out-col of W, c4 = k base
        float4 v = *(const float4*)(Wm + (size_t)i4 * 4);
        __half hx = __float2half_rn(v.x), hy = __float2half_rn(v.y);
        __half hz = __float2half_rn(v.z), hw_ = __float2half_rn(v.w);
        __half2 ph0 = __halves2half2(hx, hy), ph1 = __halves2half2(hz, hw_);
        __half lx = __float2half_rn(v.x - __half2float(hx));
        __half ly = __float2half_rn(v.y - __half2float(hy));
        __half lz = __float2half_rn(v.z - __half2float(hz));
        __half lw = __float2half_rn(v.w - __half2float(hw_));
        __half2 pl0 = __halves2half2(lx, ly), pl1 = __halves2half2(lz, lw);
        uint2 uh, ul;
        uh.x = *(unsigned*)&ph0; uh.y = *(unsigned*)&ph1;
        ul.x = *(unsigned*)&pl0; ul.y = *(unsigned*)&pl1;
        *(uint2*)(sWhi + row * WS + c4) = uh;
        *(uint2*)(sWlo + row * WS + c4) = ul;
    }
    // ---- convert A (32 rows x 128 = 1024 float4): 4 per thread ----
#pragma unroll
    for (int j = 0; j < 4; j++) {
        int i4 = tid + j * 256;
        int row = i4 >> 5, c4 = (i4 & 31) * 4;
        float4 v = *(const float4*)(h + (size_t)row0 * D + (size_t)i4 * 4);
        __half hx = __float2half_rn(v.x), hy = __float2half_rn(v.y);
        __half hz = __float2half_rn(v.z), hw_ = __float2half_rn(v.w);
        __half2 ph0 = __halves2half2(hx, hy), ph1 = __halves2half2(hz, hw_);
        __half lx = __float2half_rn(v.x - __half2float(hx));
        __half ly = __float2half_rn(v.y - __half2float(hy));
        __half lz = __float2half_rn(v.z - __half2float(hz));
        __half lw = __float2half_rn(v.w - __half2float(hw_));
        __half2 pl0 = __halves2half2(lx, ly), pl1 = __halves2half2(lz, lw);
        uint2 uh, ul;
        uh.x = *(unsigned*)&ph0; uh.y = *(unsigned*)&ph1;
        ul.x = *(unsigned*)&pl0; ul.y = *(unsigned*)&pl1;
        *(uint2*)(sAhi + row * WS + c4) = uh;
        *(uint2*)(sAlo + row * WS + c4) = ul;
    }
    __syncthreads();

    // ---- wmma: warp w -> col-tile w; row-tiles 0,1 ----
    int ct = warpId;
#pragma unroll
    for (int rt = 0; rt < 2; rt++) {
        wmma::fragment<wmma::accumulator, 16, 16, 16, float> acc;
        wmma::fill_fragment(acc, 0.f);
#pragma unroll
        for (int k0 = 0; k0 < 8; k0++) {
            wmma::fragment<wmma::matrix_a, 16, 16, 16, __half, wmma::row_major> ahi, alo;
            wmma::load_matrix_sync(ahi, sAhi + rt * 16 * WS + k0 * 16, WS);
            wmma::load_matrix_sync(alo, sAlo + rt * 16 * WS + k0 * 16, WS);
            wmma::fragment<wmma::matrix_b, 16, 16, 16, __half, wmma::col_major> bhi, blo;
            wmma::load_matrix_sync(bhi, sWhi + ct * 16 * WS + k0 * 16, WS);
            wmma::load_matrix_sync(blo, sWlo + ct * 16 * WS + k0 * 16, WS);
            wmma::mma_sync(acc, ahi, bhi, acc);
            wmma::mma_sync(acc, ahi, blo, acc);
            wmma::mma_sync(acc, alo, bhi, acc);
        }
        wmma::store_matrix_sync(sC + rt * 16 * CS + ct * 16, acc, CS, wmma::mem_row_major);
    }
    __syncthreads();

    // ---- epilogue (all from fp32 sC) ----
    // fp16 store of hw: 4 float4-groups per thread
#pragma unroll
    for (int j = 0; j < 4; j++) {
        int i4 = tid + j * 256;
        int row = i4 >> 5, off = (i4 & 31) * 4;
        float4 v = *(const float4*)(sC + row * CS + off);
        __half2 q0 = __floats2half2_rn(v.x, v.y);
        __half2 q1 = __floats2half2_rn(v.z, v.w);
        uint2 u;
        u.x = *(unsigned*)&q0; u.y = *(unsigned*)&q1;
        *(uint2*)(g_hwh + (size_t)(row0 + row) * D + off) = u;
    }
    // s1/s2: warp w owns rows 4w..4w+3; lane dots 4 cols, shfl-reduce (exact fp32)
    {
        float4 a1 = *(const float4*)(att + lane * 4);
        float4 a2 = *(const float4*)(att + D + lane * 4);
#pragma unroll
        for (int r = 0; r < 4; r++) {
            int row = warpId * 4 + r;
            float4 cv = *(const float4*)(sC + row * CS + lane * 4);
            float s1 = cv.x * a1.x + cv.y * a1.y + cv.z * a1.z + cv.w * a1.w;
            float s2 = cv.x * a2.x + cv.y * a2.y + cv.z * a2.z + cv.w * a2.w;
#pragma unroll
            for (int o = 16; o; o >>= 1) {
                s1 += __shfl_xor_sync(0xffffffffu, s1, o);
                s2 += __shfl_xor_sync(0xffffffffu, s2, o);
            }
            if (lane == 0) { g_s1[row0 + row] = s1; g_s2[row0 + row] = s2; }
        }
    }
    // colsum partial: threads 0..127, column tid over 32 rows (conflict-free)
    if (tid < D) {
        float s = 0.f;
#pragma unroll 8
        for (int r = 0; r < 32; r++) s += sC[r * CS + tid];
        g_Spart[blockIdx.x * D + tid] = s;
    }
}

// =================== K2: per-edge logit + hash insert (dedup by atomicMax) ===
// Record: bits[0:16)=half(w), [16:29)=dst, [29:48)=edge_idx+1  (max idx wins)
__global__ void k_scatter(const int* __restrict__ e32) {
    // block 0: reduce colsum partials -> g_S (k_row reads it later)
    if (blockIdx.x == 0 && threadIdx.x < D) {
        float s = 0.f;
#pragma unroll 16
        for (int b = 0; b < GB; b++) s += g_Spart[b * D + threadIdx.x];
        g_S[threadIdx.x] = s;
    }
    int e = blockIdx.x * blockDim.x + threadIdx.x;
    if (e >= E) return;
    int src, dst;
    if (g_is64) {
        src = ((const int2*)e32)[e].x;
        dst = ((const int2*)e32)[E + e].x;
    } else {
        src = e32[e];
        dst = e32[E + e];
    }
    float a = g_s1[src] + g_s2[dst];
    a = a > 0.f ? a : 0.2f * a;                       // LeakyReLU(0.2)
    float w = expm1f(a);                              // exp(a) - 1
    unsigned wh = (unsigned)__half_as_ushort(__float2half_rn(w));
    unsigned long long rec = ((unsigned long long)(unsigned)(e + 1) << 29)
                           | ((unsigned long long)(unsigned)dst << 16) | wh;
    unsigned slot = ((unsigned)dst * 2654435761u) >> 25;   // 7-bit hash
    unsigned long long* tab = g_ew64 + (size_t)src * SLOTS;
    for (int probe = 0; probe < SLOTS; probe++) {
        unsigned long long old = atomicCAS(&tab[slot], 0ULL, rec);
        if (old == 0ULL) break;                            // claimed empty slot
        if (((unsigned)(old >> 16) & 0x1FFFu) == (unsigned)dst) {
            atomicMax(&tab[slot], rec);                    // last-write-wins
            break;
        }
        slot = (slot + 1) & (SLOTS - 1);
    }
}

// =================== K3: slot scan + compact + gather + normalize ============
__global__ void __launch_bounds__(256, 5) k_row(float* __restrict__ out) {
    __shared__ uint2 sm[8][SLOTS];     // {dst, float bits of w}
    int wid = threadIdx.x >> 5, lane = threadIdx.x & 31;
    int row = blockIdx.x * 8 + wid;
    unsigned long long* tab = g_ew64 + (size_t)row * SLOTS;

    float dsum = 0.f;
    int cnt = 0;
#pragma unroll
    for (int rnd = 0; rnd < SLOTS / 32; rnd++) {
        int s = rnd * 32 + lane;
        unsigned long long v = tab[s];
        tab[s] = 0ULL;                                   // replay-safe re-zero
        unsigned mask = __ballot_sync(0xffffffffu, v != 0ULL);
        if (v != 0ULL) {
            int pos = cnt + __popc(mask & ((1u << lane) - 1u));
            float w = __half2float(__ushort_as_half((unsigned short)(v & 0xFFFFu)));
            sm[wid][pos] = make_uint2((unsigned)(v >> 16) & 0x1FFFu,
                                      __float_as_uint(w));
            dsum += w;
        }
        cnt += __popc(mask);
    }
    int dpad = (cnt + 7) & ~7;
    for (int t = cnt + lane; t < dpad; t += 32)
        sm[wid][t] = make_uint2(0u, 0u);                 // harmless pad (w=0)
    __syncwarp();

    // pair-gather: lanes 0-15 edge A, 16-31 edge B; 16B (8 halves) per lane
    float acc[8];
#pragma unroll
    for (int i = 0; i < 8; i++) acc[i] = 0.f;
    int half_ = lane >> 4;
    int cl = (lane & 15) * 8;
    const __half* hw = g_hwh;

    for (int t = 0; t < dpad; t += 8) {
#pragma unroll
        for (int p = 0; p < 4; p++) {
            uint2 m = sm[wid][t + 2 * p + half_];
            float w = __uint_as_float(m.y);
            uint4 v = *(const uint4*)(hw + (size_t)m.x * D + cl);
            float2 f0 = __half22float2(*(__half2*)&v.x);
            float2 f1 = __half22float2(*(__half2*)&v.y);
            float2 f2 = __half22float2(*(__half2*)&v.z);
            float2 f3 = __half22float2(*(__half2*)&v.w);
            acc[0] += w * f0.x; acc[1] += w * f0.y;
            acc[2] += w * f1.x; acc[3] += w * f1.y;
            acc[4] += w * f2.x; acc[5] += w * f2.y;
            acc[6] += w * f3.x; acc[7] += w * f3.y;
        }
    }

#pragma unroll
    for (int i = 0; i < 8; i++) acc[i] += __shfl_xor_sync(0xffffffffu, acc[i], 16);
#pragma unroll
    for (int o = 16; o; o >>= 1) dsum += __shfl_xor_sync(0xffffffffu, dsum, o);

    float inv = 1.f / ((float)V + dsum);
    if (lane < 16) {
        float4 Sa = *(const float4*)(g_S + cl);
        float4 Sb = *(const float4*)(g_S + cl + 4);
        float4 o0, o1;
        o0.x = (Sa.x + acc[0]) * inv; o0.y = (Sa.y + acc[1]) * inv;
        o0.z = (Sa.z + acc[2]) * inv; o0.w = (Sa.w + acc[3]) * inv;
        o1.x = (Sb.x + acc[4]) * inv; o1.y = (Sb.y + acc[5]) * inv;
        o1.z = (Sb.z + acc[6]) * inv; o1.w = (Sb.w + acc[7]) * inv;
        *(float4*)(out + (size_t)row * D + cl) = o0;
        *(float4*)(out + (size_t)row * D + cl + 4) = o1;
    }
}

// ----------------------------------------------------------------------------
extern "C" void kernel_launch(void* const* d_in, const int* in_sizes, int n_in,
                              void* d_out, int out_size) {
    const float* h   = (const float*)d_in[0];
    const int*   ei  = (const int*)d_in[1];
    const float* Wm  = (const float*)d_in[2];
    const float* att = (const float*)d_in[3];
    float* out = (float*)d_out;

    cudaFuncSetAttribute(k_gemm, cudaFuncAttributeMaxDynamicSharedMemorySize,
                         GEMM_SMEM_BYTES);
    k_gemm<<<GB, 256, GEMM_SMEM_BYTES>>>(h, Wm, att, ei);
    k_scatter<<<E / 256, 256>>>(ei);
    k_row<<<V / 8, 256>>>(out);
}

// round 14
// speedup vs baseline: 1.3816x; 1.0910x over previous
#include <cuda_runtime.h>
#include <cuda_fp16.h>
#include <mma.h>
using namespace nvcuda;

#define V 8192
#define E 262144
#define D 128
#define SLOTS 128           // hash slots per row (power of 2)
#define GB 256              // gemm grid: V / 32 rows per block

// padded smem strides (bank-conflict-free for LDSM: stride mod 128B == 16B)
#define WS 136              // half stride for W/A tiles  (272 B)
#define CS 132              // float stride for C tile    (528 B)

// dynamic smem: Whi+Wlo (2*128*136*2) + Ahi+Alo (2*32*136*2) + C (32*132*4)
#define GEMM_SMEM_BYTES (2*128*WS*2 + 2*32*WS*2 + 32*CS*4)

// ---------------- scratch (device globals; no allocations allowed) ----------
__device__ __half             g_hwh[V * D];      // hw in fp16 (2 MB, L2-resident)
__device__ __half             g_Whi[D * D];      // W hi split (pre-converted once)
__device__ __half             g_Wlo[D * D];      // W lo split
__device__ float              g_s1[V];           // hw[v] . att[:128]  (exact fp32)
__device__ float              g_s2[V];           // hw[v] . att[128:]
__device__ float              g_Spart[GB * D];   // per-block colsum partials
__device__ float              g_S[D];            // reduced colsum of hw
__device__ unsigned long long g_ew64[(size_t)V * SLOTS]; // (idx+1)<<29|dst<<16|half(w)
__device__ int                g_is64;            // edge_index dtype flag

// =================== K0: W fp16-split (once) + dtype detection ===============
// grid 16 x 256: thread i handles float4 i of W (4096 total). Block 0 also
// detects int64 vs int32 edge_index (int64 values < 2^13 => odd words all 0).
__global__ void k_prep(const float* __restrict__ Wm, const int* __restrict__ e32) {
    int tid = threadIdx.x;
    if (blockIdx.x == 0) {
        __shared__ int flag;
        if (tid == 0) flag = 0;
        __syncthreads();
        if (e32[2 * tid + 1] != 0) atomicExch(&flag, 1);
        __syncthreads();
        if (tid == 0) g_is64 = (flag == 0) ? 1 : 0;
    }
    int i4 = blockIdx.x * 256 + tid;              // 0..4095
    float4 v = ((const float4*)Wm)[i4];
    __half hx = __float2half_rn(v.x), hy = __float2half_rn(v.y);
    __half hz = __float2half_rn(v.z), hw_ = __float2half_rn(v.w);
    __half2 ph0 = __halves2half2(hx, hy), ph1 = __halves2half2(hz, hw_);
    __half lx = __float2half_rn(v.x - __half2float(hx));
    __half ly = __float2half_rn(v.y - __half2float(hy));
    __half lz = __float2half_rn(v.z - __half2float(hz));
    __half lw = __float2half_rn(v.w - __half2float(hw_));
    __half2 pl0 = __halves2half2(lx, ly), pl1 = __halves2half2(lz, lw);
    uint2 uh, ul;
    uh.x = *(unsigned*)&ph0; uh.y = *(unsigned*)&ph1;
    ul.x = *(unsigned*)&pl0; ul.y = *(unsigned*)&pl1;
    *(uint2*)(g_Whi + (size_t)i4 * 4) = uh;
    *(uint2*)(g_Wlo + (size_t)i4 * 4) = ul;
}

// =================== K1: tensor-core GEMM hw = h @ W^T (fp16-split, smem) ====
// Block: 32 rows x 128 cols. Pre-split W copied fp16->smem (no conversion);
// A rows converted hi/lo per block. 8 warps: warp w owns col-tile w, 2 row-
// tiles, K loop 8x16, 3 HMMA per step (missing lo*lo term ~2^-22 relative).
// Accumulators staged in fp32 smem; epilogue: fp16 store + exact s1/s2 + colsum.
__global__ void __launch_bounds__(256) k_gemm(const float* __restrict__ h,
                                              const float* __restrict__ att) {
    extern __shared__ char dynsmem[];
    __half* sWhi = (__half*)dynsmem;              // [128][WS]  W[col][k]
    __half* sWlo = sWhi + 128 * WS;
    __half* sAhi = sWlo + 128 * WS;               // [32][WS]
    __half* sAlo = sAhi + 32 * WS;
    float*  sC   = (float*)(sAlo + 32 * WS);      // [32][CS] fp32 result

    int tid = threadIdx.x;
    int warpId = tid >> 5, lane = tid & 31;
    int row0 = blockIdx.x * 32;

    // ---- copy pre-split W into padded smem: 2048 uint4 per array, 8/thread
    const uint4* Wh4 = (const uint4*)g_Whi;
    const uint4* Wl4 = (const uint4*)g_Wlo;
#pragma unroll
    for (int j = 0; j < 8; j++) {
        int i = tid + j * 256;                    // 0..2047
        int row = i >> 4, c8 = (i & 15) * 8;      // 16 uint4 (128 halves) per row
        *(uint4*)(sWhi + row * WS + c8) = Wh4[i];
        *(uint4*)(sWlo + row * WS + c8) = Wl4[i];
    }
    // ---- convert A (32 rows x 128 = 1024 float4): 4 per thread ----
#pragma unroll
    for (int j = 0; j < 4; j++) {
        int i4 = tid + j * 256;
        int row = i4 >> 5, c4 = (i4 & 31) * 4;
        float4 v = *(const float4*)(h + (size_t)row0 * D + (size_t)i4 * 4);
        __half hx = __float2half_rn(v.x), hy = __float2half_rn(v.y);
        __half hz = __float2half_rn(v.z), hw_ = __float2half_rn(v.w);
        __half2 ph0 = __halves2half2(hx, hy), ph1 = __halves2half2(hz, hw_);
        __half lx = __float2half_rn(v.x - __half2float(hx));
        __half ly = __float2half_rn(v.y - __half2float(hy));
        __half lz = __float2half_rn(v.z - __half2float(hz));
        __half lw = __float2half_rn(v.w - __half2float(hw_));
        __half2 pl0 = __halves2half2(lx, ly), pl1 = __halves2half2(lz, lw);
        uint2 uh, ul;
        uh.x = *(unsigned*)&ph0; uh.y = *(unsigned*)&ph1;
        ul.x = *(unsigned*)&pl0; ul.y = *(unsigned*)&pl1;
        *(uint2*)(sAhi + row * WS + c4) = uh;
        *(uint2*)(sAlo + row * WS + c4) = ul;
    }
    __syncthreads();

    // ---- wmma: warp w -> col-tile w; row-tiles 0,1 ----
    int ct = warpId;
#pragma unroll
    for (int rt = 0; rt < 2; rt++) {
        wmma::fragment<wmma::accumulator, 16, 16, 16, float> acc;
        wmma::fill_fragment(acc, 0.f);
#pragma unroll
        for (int k0 = 0; k0 < 8; k0++) {
            wmma::fragment<wmma::matrix_a, 16, 16, 16, __half, wmma::row_major> ahi, alo;
            wmma::load_matrix_sync(ahi, sAhi + rt * 16 * WS + k0 * 16, WS);
            wmma::load_matrix_sync(alo, sAlo + rt * 16 * WS + k0 * 16, WS);
            wmma::fragment<wmma::matrix_b, 16, 16, 16, __half, wmma::col_major> bhi, blo;
            wmma::load_matrix_sync(bhi, sWhi + ct * 16 * WS + k0 * 16, WS);
            wmma::load_matrix_sync(blo, sWlo + ct * 16 * WS + k0 * 16, WS);
            wmma::mma_sync(acc, ahi, bhi, acc);
            wmma::mma_sync(acc, ahi, blo, acc);
            wmma::mma_sync(acc, alo, bhi, acc);
        }
        wmma::store_matrix_sync(sC + rt * 16 * CS + ct * 16, acc, CS, wmma::mem_row_major);
    }
    __syncthreads();

    // ---- epilogue (all from fp32 sC) ----
#pragma unroll
    for (int j = 0; j < 4; j++) {
        int i4 = tid + j * 256;
        int row = i4 >> 5, off = (i4 & 31) * 4;
        float4 v = *(const float4*)(sC + row * CS + off);
        __half2 q0 = __floats2half2_rn(v.x, v.y);
        __half2 q1 = __floats2half2_rn(v.z, v.w);
        uint2 u;
        u.x = *(unsigned*)&q0; u.y = *(unsigned*)&q1;
        *(uint2*)(g_hwh + (size_t)(row0 + row) * D + off) = u;
    }
    // s1/s2: warp w owns rows 4w..4w+3; lane dots 4 cols, shfl-reduce (exact fp32)
    {
        float4 a1 = *(const float4*)(att + lane * 4);
        float4 a2 = *(const float4*)(att + D + lane * 4);
#pragma unroll
        for (int r = 0; r < 4; r++) {
            int row = warpId * 4 + r;
            float4 cv = *(const float4*)(sC + row * CS + lane * 4);
            float s1 = cv.x * a1.x + cv.y * a1.y + cv.z * a1.z + cv.w * a1.w;
            float s2 = cv.x * a2.x + cv.y * a2.y + cv.z * a2.z + cv.w * a2.w;
#pragma unroll
            for (int o = 16; o; o >>= 1) {
                s1 += __shfl_xor_sync(0xffffffffu, s1, o);
                s2 += __shfl_xor_sync(0xffffffffu, s2, o);
            }
            if (lane == 0) { g_s1[row0 + row] = s1; g_s2[row0 + row] = s2; }
        }
    }
    // colsum partial: threads 0..127, column tid over 32 rows (conflict-free)
    if (tid < D) {
        float s = 0.f;
#pragma unroll 8
        for (int r = 0; r < 32; r++) s += sC[r * CS + tid];
        g_Spart[blockIdx.x * D + tid] = s;
    }
}

// =================== K2: per-edge logit + hash insert (dedup by atomicMax) ===
// Record: bits[0:16)=half(w), [16:29)=dst, [29:48)=edge_idx+1  (max idx wins)
__global__ void k_scatter(const int* __restrict__ e32) {
    // block 0: reduce colsum partials -> g_S (k_row reads it later)
    if (blockIdx.x == 0 && threadIdx.x < D) {
        float s = 0.f;
#pragma unroll 16
        for (int b = 0; b < GB; b++) s += g_Spart[b * D + threadIdx.x];
        g_S[threadIdx.x] = s;
    }
    int e = blockIdx.x * blockDim.x + threadIdx.x;
    if (e >= E) return;
    int src, dst;
    if (g_is64) {
        src = ((const int2*)e32)[e].x;
        dst = ((const int2*)e32)[E + e].x;
    } else {
        src = e32[e];
        dst = e32[E + e];
    }
    float a = g_s1[src] + g_s2[dst];
    a = a > 0.f ? a : 0.2f * a;                       // LeakyReLU(0.2)
    float w = expm1f(a);                              // exp(a) - 1
    unsigned wh = (unsigned)__half_as_ushort(__float2half_rn(w));
    unsigned long long rec = ((unsigned long long)(unsigned)(e + 1) << 29)
                           | ((unsigned long long)(unsigned)dst << 16) | wh;
    unsigned slot = ((unsigned)dst * 2654435761u) >> 25;   // 7-bit hash
    unsigned long long* tab = g_ew64 + (size_t)src * SLOTS;
    for (int probe = 0; probe < SLOTS; probe++) {
        unsigned long long old = atomicCAS(&tab[slot], 0ULL, rec);
        if (old == 0ULL) break;                            // claimed empty slot
        if (((unsigned)(old >> 16) & 0x1FFFu) == (unsigned)dst) {
            atomicMax(&tab[slot], rec);                    // last-write-wins
            break;
        }
        slot = (slot + 1) & (SLOTS - 1);
    }
}

// =================== K3: slot scan + compact + pipelined gather ==============
__global__ void __launch_bounds__(256, 4) k_row(float* __restrict__ out) {
    __shared__ uint2 sm[8][SLOTS];     // {dst, float bits of w}
    int wid = threadIdx.x >> 5, lane = threadIdx.x & 31;
    int row = blockIdx.x * 8 + wid;
    unsigned long long* tab = g_ew64 + (size_t)row * SLOTS;

    float dsum = 0.f;
    int cnt = 0;
#pragma unroll
    for (int rnd = 0; rnd < SLOTS / 32; rnd++) {
        int s = rnd * 32 + lane;
        unsigned long long v = tab[s];
        tab[s] = 0ULL;                                   // replay-safe re-zero
        unsigned mask = __ballot_sync(0xffffffffu, v != 0ULL);
        if (v != 0ULL) {
            int pos = cnt + __popc(mask & ((1u << lane) - 1u));
            float w = __half2float(__ushort_as_half((unsigned short)(v & 0xFFFFu)));
            sm[wid][pos] = make_uint2((unsigned)(v >> 16) & 0x1FFFu,
                                      __float_as_uint(w));
            dsum += w;
        }
        cnt += __popc(mask);
    }
    int dpad = (cnt + 7) & ~7;
    for (int t = cnt + lane; t < dpad; t += 32)
        sm[wid][t] = make_uint2(0u, 0u);                 // harmless pad (w=0)
    __syncwarp();

    // pipelined pair-gather: lanes 0-15 edge A, 16-31 edge B; 16B per lane;
    // prefetch next 4-pair group while accumulating current (MLP 8).
    float acc[8];
#pragma unroll
    for (int i = 0; i < 8; i++) acc[i] = 0.f;
    int half_ = lane >> 4;
    int cl = (lane & 15) * 8;
    const __half* hw = g_hwh;

    uint2 mcur[4]; uint4 vcur[4];
    if (dpad > 0) {
#pragma unroll
        for (int p = 0; p < 4; p++) {
            mcur[p] = sm[wid][2 * p + half_];
            vcur[p] = *(const uint4*)(hw + (size_t)mcur[p].x * D + cl);
        }
    }
    for (int t = 0; t < dpad; t += 8) {
        uint2 mn[4]; uint4 vn[4];
        bool more = (t + 8 < dpad);
        if (more) {
#pragma unroll
            for (int p = 0; p < 4; p++) {
                mn[p] = sm[wid][t + 8 + 2 * p + half_];
                vn[p] = *(const uint4*)(hw + (size_t)mn[p].x * D + cl);
            }
        }
#pragma unroll
        for (int p = 0; p < 4; p++) {
            float w = __uint_as_float(mcur[p].y);
            float2 f0 = __half22float2(*(__half2*)&vcur[p].x);
            float2 f1 = __half22float2(*(__half2*)&vcur[p].y);
            float2 f2 = __half22float2(*(__half2*)&vcur[p].z);
            float2 f3 = __half22float2(*(__half2*)&vcur[p].w);
            acc[0] += w * f0.x; acc[1] += w * f0.y;
            acc[2] += w * f1.x; acc[3] += w * f1.y;
            acc[4] += w * f2.x; acc[5] += w * f2.y;
            acc[6] += w * f3.x; acc[7] += w * f3.y;
        }
        if (more) {
#pragma unroll
            for (int p = 0; p < 4; p++) { mcur[p] = mn[p]; vcur[p] = vn[p]; }
        }
    }

#pragma unroll
    for (int i = 0; i < 8; i++) acc[i] += __shfl_xor_sync(0xffffffffu, acc[i], 16);
#pragma unroll
    for (int o = 16; o; o >>= 1) dsum += __shfl_xor_sync(0xffffffffu, dsum, o);

    float inv = 1.f / ((float)V + dsum);
    if (lane < 16) {
        float4 Sa = *(const float4*)(g_S + cl);
        float4 Sb = *(const float4*)(g_S + cl + 4);
        float4 o0, o1;
        o0.x = (Sa.x + acc[0]) * inv; o0.y = (Sa.y + acc[1]) * inv;
        o0.z = (Sa.z + acc[2]) * inv; o0.w = (Sa.w + acc[3]) * inv;
        o1.x = (Sb.x + acc[4]) * inv; o1.y = (Sb.y + acc[5]) * inv;
        o1.z = (Sb.z + acc[6]) * inv; o1.w = (Sb.w + acc[7]) * inv;
        *(float4*)(out + (size_t)row * D + cl) = o0;
        *(float4*)(out + (size_t)row * D + cl + 4) = o1;
    }
}

// ----------------------------------------------------------------------------
extern "C" void kernel_launch(void* const* d_in, const int* in_sizes, int n_in,
                              void* d_out, int out_size) {
    const float* h   = (const float*)d_in[0];
    const int*   ei  = (const int*)d_in[1];
    const float* Wm  = (const float*)d_in[2];
    const float* att = (const float*)d_in[3];
    float* out = (float*)d_out;

    cudaFuncSetAttribute(k_gemm, cudaFuncAttributeMaxDynamicSharedMemorySize,
                         GEMM_SMEM_BYTES);
    k_prep<<<16, 256>>>(Wm, ei);
    k_gemm<<<GB, 256, GEMM_SMEM_BYTES>>>(h, att);
    k_scatter<<<E / 256, 256>>>(ei);
    k_row<<<V / 8, 256>>>(out);
}

// round 15
// speedup vs baseline: 1.4212x; 1.0287x over previous
#include <cuda_runtime.h>
#include <cuda_fp16.h>
#include <mma.h>
using namespace nvcuda;

#define V 8192
#define E 262144
#define D 128
#define SLOTS 128           // hash slots per row (power of 2)
#define GB 256              // gemm grid: V / 32 rows per block

// padded smem strides (bank-conflict-free for LDSM: stride mod 128B == 16B)
#define WS 136              // half stride for W/A tiles  (272 B)
#define CS 132              // float stride for C tile    (528 B)

// dynamic smem: Whi+Wlo (2*128*136*2) + Ahi+Alo (2*32*136*2) + C (32*132*4)
#define GEMM_SMEM_BYTES (2*128*WS*2 + 2*32*WS*2 + 32*CS*4)

// ---------------- scratch (device globals; no allocations allowed) ----------
__device__ __half             g_hwh[V * D];      // hw in fp16 (2 MB, L2-resident)
__device__ __half             g_Whi[D * D];      // W hi split (pre-converted once)
__device__ __half             g_Wlo[D * D];      // W lo split
__device__ float              g_s1[V];           // hw[v] . att[:128]  (exact fp32)
__device__ float              g_s2[V];           // hw[v] . att[128:]
__device__ float              g_Spart[GB * D];   // per-block colsum partials
__device__ float              g_S[D];            // reduced colsum of hw
__device__ unsigned           g_ew32[(size_t)V * SLOTS]; // (idx+1)<<13 | dst
__device__ int                g_is64;            // edge_index dtype flag

// =================== K0: W fp16-split (once) + dtype detection ===============
__global__ void k_prep(const float* __restrict__ Wm, const int* __restrict__ e32) {
    int tid = threadIdx.x;
    if (blockIdx.x == 0) {
        __shared__ int flag;
        if (tid == 0) flag = 0;
        __syncthreads();
        if (e32[2 * tid + 1] != 0) atomicExch(&flag, 1);
        __syncthreads();
        if (tid == 0) g_is64 = (flag == 0) ? 1 : 0;
    }
    int i4 = blockIdx.x * 256 + tid;              // 0..4095
    float4 v = ((const float4*)Wm)[i4];
    __half hx = __float2half_rn(v.x), hy = __float2half_rn(v.y);
    __half hz = __float2half_rn(v.z), hw_ = __float2half_rn(v.w);
    __half2 ph0 = __halves2half2(hx, hy), ph1 = __halves2half2(hz, hw_);
    __half lx = __float2half_rn(v.x - __half2float(hx));
    __half ly = __float2half_rn(v.y - __half2float(hy));
    __half lz = __float2half_rn(v.z - __half2float(hz));
    __half lw = __float2half_rn(v.w - __half2float(hw_));
    __half2 pl0 = __halves2half2(lx, ly), pl1 = __halves2half2(lz, lw);
    uint2 uh, ul;
    uh.x = *(unsigned*)&ph0; uh.y = *(unsigned*)&ph1;
    ul.x = *(unsigned*)&pl0; ul.y = *(unsigned*)&pl1;
    *(uint2*)(g_Whi + (size_t)i4 * 4) = uh;
    *(uint2*)(g_Wlo + (size_t)i4 * 4) = ul;
}

// =================== K1: tensor-core GEMM hw = h @ W^T (fp16-split, smem) ====
__global__ void __launch_bounds__(256) k_gemm(const float* __restrict__ h,
                                              const float* __restrict__ att) {
    extern __shared__ char dynsmem[];
    __half* sWhi = (__half*)dynsmem;              // [128][WS]  W[col][k]
    __half* sWlo = sWhi + 128 * WS;
    __half* sAhi = sWlo + 128 * WS;               // [32][WS]
    __half* sAlo = sAhi + 32 * WS;
    float*  sC   = (float*)(sAlo + 32 * WS);      // [32][CS] fp32 result

    int tid = threadIdx.x;
    int warpId = tid >> 5, lane = tid & 31;
    int row0 = blockIdx.x * 32;

    // ---- copy pre-split W into padded smem: 2048 uint4 per array, 8/thread
    const uint4* Wh4 = (const uint4*)g_Whi;
    const uint4* Wl4 = (const uint4*)g_Wlo;
#pragma unroll
    for (int j = 0; j < 8; j++) {
        int i = tid + j * 256;                    // 0..2047
        int row = i >> 4, c8 = (i & 15) * 8;
        *(uint4*)(sWhi + row * WS + c8) = Wh4[i];
        *(uint4*)(sWlo + row * WS + c8) = Wl4[i];
    }
    // ---- convert A (32 rows x 128 = 1024 float4): 4 per thread ----
#pragma unroll
    for (int j = 0; j < 4; j++) {
        int i4 = tid + j * 256;
        int row = i4 >> 5, c4 = (i4 & 31) * 4;
        float4 v = *(const float4*)(h + (size_t)row0 * D + (size_t)i4 * 4);
        __half hx = __float2half_rn(v.x), hy = __float2half_rn(v.y);
        __half hz = __float2half_rn(v.z), hw_ = __float2half_rn(v.w);
        __half2 ph0 = __halves2half2(hx, hy), ph1 = __halves2half2(hz, hw_);
        __half lx = __float2half_rn(v.x - __half2float(hx));
        __half ly = __float2half_rn(v.y - __half2float(hy));
        __half lz = __float2half_rn(v.z - __half2float(hz));
        __half lw = __float2half_rn(v.w - __half2float(hw_));
        __half2 pl0 = __halves2half2(lx, ly), pl1 = __halves2half2(lz, lw);
        uint2 uh, ul;
        uh.x = *(unsigned*)&ph0; uh.y = *(unsigned*)&ph1;
        ul.x = *(unsigned*)&pl0; ul.y = *(unsigned*)&pl1;
        *(uint2*)(sAhi + row * WS + c4) = uh;
        *(uint2*)(sAlo + row * WS + c4) = ul;
    }
    __syncthreads();

    // ---- wmma: warp w -> col-tile w; row-tiles 0,1 ----
    int ct = warpId;
#pragma unroll
    for (int rt = 0; rt < 2; rt++) {
        wmma::fragment<wmma::accumulator, 16, 16, 16, float> acc;
        wmma::fill_fragment(acc, 0.f);
#pragma unroll
        for (int k0 = 0; k0 < 8; k0++) {
            wmma::fragment<wmma::matrix_a, 16, 16, 16, __half, wmma::row_major> ahi, alo;
            wmma::load_matrix_sync(ahi, sAhi + rt * 16 * WS + k0 * 16, WS);
            wmma::load_matrix_sync(alo, sAlo + rt * 16 * WS + k0 * 16, WS);
            wmma::fragment<wmma::matrix_b, 16, 16, 16, __half, wmma::col_major> bhi, blo;
            wmma::load_matrix_sync(bhi, sWhi + ct * 16 * WS + k0 * 16, WS);
            wmma::load_matrix_sync(blo, sWlo + ct * 16 * WS + k0 * 16, WS);
            wmma::mma_sync(acc, ahi, bhi, acc);
            wmma::mma_sync(acc, ahi, blo, acc);
            wmma::mma_sync(acc, alo, bhi, acc);
        }
        wmma::store_matrix_sync(sC + rt * 16 * CS + ct * 16, acc, CS, wmma::mem_row_major);
    }
    __syncthreads();

    // ---- epilogue (all from fp32 sC) ----
#pragma unroll
    for (int j = 0; j < 4; j++) {
        int i4 = tid + j * 256;
        int row = i4 >> 5, off = (i4 & 31) * 4;
        float4 v = *(const float4*)(sC + row * CS + off);
        __half2 q0 = __floats2half2_rn(v.x, v.y);
        __half2 q1 = __floats2half2_rn(v.z, v.w);
        uint2 u;
        u.x = *(unsigned*)&q0; u.y = *(unsigned*)&q1;
        *(uint2*)(g_hwh + (size_t)(row0 + row) * D + off) = u;
    }
    // s1/s2: warp w owns rows 4w..4w+3; lane dots 4 cols, shfl-reduce (exact fp32)
    {
        float4 a1 = *(const float4*)(att + lane * 4);
        float4 a2 = *(const float4*)(att + D + lane * 4);
#pragma unroll
        for (int r = 0; r < 4; r++) {
            int row = warpId * 4 + r;
            float4 cv = *(const float4*)(sC + row * CS + lane * 4);
            float s1 = cv.x * a1.x + cv.y * a1.y + cv.z * a1.z + cv.w * a1.w;
            float s2 = cv.x * a2.x + cv.y * a2.y + cv.z * a2.z + cv.w * a2.w;
#pragma unroll
            for (int o = 16; o; o >>= 1) {
                s1 += __shfl_xor_sync(0xffffffffu, s1, o);
                s2 += __shfl_xor_sync(0xffffffffu, s2, o);
            }
            if (lane == 0) { g_s1[row0 + row] = s1; g_s2[row0 + row] = s2; }
        }
    }
    // colsum partial: threads 0..127, column tid over 32 rows (conflict-free)
    if (tid < D) {
        float s = 0.f;
#pragma unroll 8
        for (int r = 0; r < 32; r++) s += sC[r * CS + tid];
        g_Spart[blockIdx.x * D + tid] = s;
    }
}

// =================== K2: hash insert only (32-bit; dedup by atomicMax) =======
// Record: bits[0:13)=dst, [13:32)=edge_idx+1. Max idx wins = last-write-wins.
// No weight math here — k_row recomputes w from s1/s2 during slot scan.
__global__ void k_scatter(const int* __restrict__ e32) {
    // block 0: reduce colsum partials -> g_S (k_row reads it later)
    if (blockIdx.x == 0 && threadIdx.x < D) {
        float s = 0.f;
#pragma unroll 16
        for (int b = 0; b < GB; b++) s += g_Spart[b * D + threadIdx.x];
        g_S[threadIdx.x] = s;
    }
    int e = blockIdx.x * blockDim.x + threadIdx.x;
    if (e >= E) return;
    int src, dst;
    if (g_is64) {
        src = ((const int2*)e32)[e].x;
        dst = ((const int2*)e32)[E + e].x;
    } else {
        src = e32[e];
        dst = e32[E + e];
    }
    unsigned rec = ((unsigned)(e + 1) << 13) | (unsigned)dst;
    unsigned slot = ((unsigned)dst * 2654435761u) >> 25;   // 7-bit hash
    unsigned* tab = g_ew32 + (size_t)src * SLOTS;
    for (int probe = 0; probe < SLOTS; probe++) {
        unsigned old = atomicCAS(&tab[slot], 0u, rec);
        if (old == 0u) break;                              // claimed empty slot
        if ((old & 0x1FFFu) == (unsigned)dst) {
            atomicMax(&tab[slot], rec);                    // last-write-wins
            break;
        }
        slot = (slot + 1) & (SLOTS - 1);
    }
}

// =================== K3: slot scan (+ weight recompute) + pipelined gather ===
__global__ void __launch_bounds__(256, 4) k_row(float* __restrict__ out) {
    __shared__ uint2 sm[8][SLOTS];     // {dst, float bits of w}
    int wid = threadIdx.x >> 5, lane = threadIdx.x & 31;
    int row = blockIdx.x * 8 + wid;
    unsigned* tab = g_ew32 + (size_t)row * SLOTS;
    float s1row = g_s1[row];

    float dsum = 0.f;
    int cnt = 0;
#pragma unroll
    for (int rnd = 0; rnd < SLOTS / 32; rnd++) {
        int s = rnd * 32 + lane;
        unsigned v = tab[s];
        tab[s] = 0u;                                     // replay-safe re-zero
        unsigned mask = __ballot_sync(0xffffffffu, v != 0u);
        if (v != 0u) {
            int pos = cnt + __popc(mask & ((1u << lane) - 1u));
            unsigned dst = v & 0x1FFFu;
            float a = s1row + g_s2[dst];
            a = a > 0.f ? a : 0.2f * a;                  // LeakyReLU(0.2)
            float w = expm1f(a);                         // exp(a) - 1 (fp32)
            sm[wid][pos] = make_uint2(dst, __float_as_uint(w));
            dsum += w;
        }
        cnt += __popc(mask);
    }
    int dpad = (cnt + 7) & ~7;
    for (int t = cnt + lane; t < dpad; t += 32)
        sm[wid][t] = make_uint2(0u, 0u);                 // harmless pad (w=0)
    __syncwarp();

    // pipelined pair-gather: lanes 0-15 edge A, 16-31 edge B; 16B per lane;
    // prefetch next 4-pair group while accumulating current (MLP 8).
    float acc[8];
#pragma unroll
    for (int i = 0; i < 8; i++) acc[i] = 0.f;
    int half_ = lane >> 4;
    int cl = (lane & 15) * 8;
    const __half* hw = g_hwh;

    uint2 mcur[4]; uint4 vcur[4];
    if (dpad > 0) {
#pragma unroll
        for (int p = 0; p < 4; p++) {
            mcur[p] = sm[wid][2 * p + half_];
            vcur[p] = *(const uint4*)(hw + (size_t)mcur[p].x * D + cl);
        }
    }
    for (int t = 0; t < dpad; t += 8) {
        uint2 mn[4]; uint4 vn[4];
        bool more = (t + 8 < dpad);
        if (more) {
#pragma unroll
            for (int p = 0; p < 4; p++) {
                mn[p] = sm[wid][t + 8 + 2 * p + half_];
                vn[p] = *(const uint4*)(hw + (size_t)mn[p].x * D + cl);
            }
        }
#pragma unroll
        for (int p = 0; p < 4; p++) {
            float w = __uint_as_float(mcur[p].y);
            float2 f0 = __half22float2(*(__half2*)&vcur[p].x);
            float2 f1 = __half22float2(*(__half2*)&vcur[p].y);
            float2 f2 = __half22float2(*(__half2*)&vcur[p].z);
            float2 f3 = __half22float2(*(__half2*)&vcur[p].w);
            acc[0] += w * f0.x; acc[1] += w * f0.y;
            acc[2] += w * f1.x; acc[3] += w * f1.y;
            acc[4] += w * f2.x; acc[5] += w * f2.y;
            acc[6] += w * f3.x; acc[7] += w * f3.y;
        }
        if (more) {
#pragma unroll
            for (int p = 0; p < 4; p++) { mcur[p] = mn[p]; vcur[p] = vn[p]; }
        }
    }

#pragma unroll
    for (int i = 0; i < 8; i++) acc[i] += __shfl_xor_sync(0xffffffffu, acc[i], 16);
#pragma unroll
    for (int o = 16; o; o >>= 1) dsum += __shfl_xor_sync(0xffffffffu, dsum, o);

    float inv = 1.f / ((float)V + dsum);
    if (lane < 16) {
        float4 Sa = *(const float4*)(g_S + cl);
        float4 Sb = *(const float4*)(g_S + cl + 4);
        float4 o0, o1;
        o0.x = (Sa.x + acc[0]) * inv; o0.y = (Sa.y + acc[1]) * inv;
        o0.z = (Sa.z + acc[2]) * inv; o0.w = (Sa.w + acc[3]) * inv;
        o1.x = (Sb.x + acc[4]) * inv; o1.y = (Sb.y + acc[5]) * inv;
        o1.z = (Sb.z + acc[6]) * inv; o1.w = (Sb.w + acc[7]) * inv;
        *(float4*)(out + (size_t)row * D + cl) = o0;
        *(float4*)(out + (size_t)row * D + cl + 4) = o1;
    }
}

// ----------------------------------------------------------------------------
extern "C" void kernel_launch(void* const* d_in, const int* in_sizes, int n_in,
                              void* d_out, int out_size) {
    const float* h   = (const float*)d_in[0];
    const int*   ei  = (const int*)d_in[1];
    const float* Wm  = (const float*)d_in[2];
    const float* att = (const float*)d_in[3];
    float* out = (float*)d_out;

    cudaFuncSetAttribute(k_gemm, cudaFuncAttributeMaxDynamicSharedMemorySize,
                         GEMM_SMEM_BYTES);
    k_prep<<<16, 256>>>(Wm, ei);
    k_gemm<<<GB, 256, GEMM_SMEM_BYTES>>>(h, att);
    k_scatter<<<E / 256, 256>>>(ei);
    k_row<<<V / 8, 256>>>(out);
}